// round 13
// baseline (speedup 1.0000x reference)
#include <cuda_runtime.h>

// ============================================================================
// RNN_29463475650831: GRU(T=11,F=3,H=11, reset_after) + Dense(121->7) + softmax
// B = 1,048,576. fp32. R13: scalar 3 elems/thread @ 168-reg budget (3 blk/SM,
// 12 warps/SM). Same slots/elem as R9's 4-elem but +50% latency coverage and
// spill-free reg headroom. Elements taken from 3 contiguous batch chunks so
// all loads/stores stay coalesced. MUFU.TANH activations.
// ============================================================================

#define NTHREADS 128
#define B_TOTAL 1048576
#define CHUNK 349526                       // ceil(B/3); chunks: [0,CH),[CH,2CH),[2CH,B)
#define NTHREADS_TOTAL CHUNK               // one thread per chunk-0 element
#define LOG2E 1.4426950408889634f

// Scalar weight image (floats): region A 48/j (11 j), D (528+), Db (1496+)
#define WTOTF 1504
__device__ __align__(16) float g_wimg[WTOTF];

// Transposed input: plane layout [t*3+f][elem]  (33 planes of B floats)
__device__ __align__(16) float g_xT[33u * B_TOTAL];   // 138 MB static scratch

// ---------------- scalar math helpers ----------------
static __device__ __forceinline__ float fex2(float x) {
    float y; asm("ex2.approx.f32 %0, %1;" : "=f"(y) : "f"(x)); return y;
}
static __device__ __forceinline__ float frcp(float x) {
    float y; asm("rcp.approx.f32 %0, %1;" : "=f"(y) : "f"(x)); return y;
}
static __device__ __forceinline__ float tnh1(float x) {       // MUFU.TANH
    float y; asm("tanh.approx.f32 %0, %1;" : "=f"(y) : "f"(x)); return y;
}
static __device__ __forceinline__ float sig1(float a) {       // 0.5+0.5*tanh(a/2)
    return fmaf(0.5f, tnh1(0.5f * a), 0.5f);
}

// ---------------- weight image builder ----------------
static __device__ __forceinline__ float wval(int i,
                                             const float* K, const float* R,
                                             const float* bias, const float* Wd,
                                             const float* db) {
    float v = 0.0f;
    if (i < 528) {
        int j = i / 48, k = i % 48;
        if      (k == 0)  v = bias[j]      + bias[33 + j];
        else if (k == 1)  v = bias[11 + j] + bias[44 + j];
        else if (k == 2)  v = bias[22 + j];
        else if (k == 3)  v = bias[55 + j];
        else if (k < 7)   v = K[(k - 4)  * 33 + j];
        else if (k < 10)  v = K[(k - 7)  * 33 + 11 + j];
        else if (k < 13)  v = K[(k - 10) * 33 + 22 + j];
        else if (k == 13) v = 0.0f;
        else if (k < 25)  v = R[(k - 14) * 33 + j];
        else if (k < 36)  v = R[(k - 25) * 33 + 11 + j];
        else if (k < 47)  v = R[(k - 36) * 33 + 22 + j];
    } else if (i < 1496) {
        int d = i - 528, c = d & 7;
        if (c < 7) v = Wd[(d >> 3) * 7 + c];
    } else {
        int c = i - 1496;
        if (c < 7) v = db[c];
    }
    return v;
}

// ---------------- kernel 1: transpose x + (block 0) build weight image ------
#define TP_ELEMS 256
__global__ __launch_bounds__(256)
void xpose_kernel(const float* __restrict__ x,
                  const float* __restrict__ K, const float* __restrict__ R,
                  const float* __restrict__ bias, const float* __restrict__ Wd,
                  const float* __restrict__ db) {
    __shared__ float tile[TP_ELEMS * 33];
    const unsigned base = blockIdx.x * (TP_ELEMS * 33u);
    #pragma unroll
    for (int k = 0; k < 33; k++) {
        int i = k * 256 + threadIdx.x;
        tile[i] = x[base + i];
    }
    if (blockIdx.x == 0) {
        for (int i = threadIdx.x; i < WTOTF; i += 256) {
            g_wimg[i] = wval(i, K, R, bias, Wd, db);
        }
    }
    __syncthreads();
    const unsigned ebase = blockIdx.x * TP_ELEMS;
    #pragma unroll 4
    for (int idx = threadIdx.x; idx < 33 * TP_ELEMS; idx += 256) {
        int plane = idx / TP_ELEMS;          // 0..32
        int el    = idx % TP_ELEMS;          // 0..255 -> coalesced write
        g_xT[(size_t)plane * B_TOTAL + ebase + el] = tile[el * 33 + plane];
    }
}

// ---------------- kernel 2: main GRU (scalar, 3 elems/thread) ---------------
__global__ __launch_bounds__(NTHREADS, 3)   // 168-reg budget, 12 warps/SM
void gru_main(float* __restrict__ out) {
    __shared__ __align__(16) float ws[WTOTF];
    {
        const float4* s = reinterpret_cast<const float4*>(g_wimg);
        float4* d = reinterpret_cast<float4*>(ws);
        #pragma unroll
        for (int i = threadIdx.x; i < WTOTF / 4; i += NTHREADS) d[i] = s[i];
    }
    __syncthreads();

    const unsigned q = blockIdx.x * NTHREADS + threadIdx.x;
    if (q >= NTHREADS_TOTAL) return;
    const unsigned ea = q;                        // chunk 0
    const unsigned eb = q + CHUNK;                // chunk 1 (always < B)
    const unsigned ecv = q + 2u * CHUNK;          // chunk 2 (may overflow by <=2)
    const bool cok = (ecv < B_TOTAL);
    const unsigned ec = cok ? ecv : (B_TOTAL - 1u);   // clamped load addr

    float ha[11], hb[11], hc[11];
    #pragma unroll
    for (int i = 0; i < 11; i++) { ha[i] = hb[i] = hc[i] = 0.0f; }

    float aca[7], acb[7], acc_[7];
    #pragma unroll
    for (int c = 0; c < 7; c++) {
        float b = ws[1496 + c];
        aca[c] = b; acb[c] = b; acc_[c] = b;
    }

    #pragma unroll 1
    for (int t = 0; t < 11; t++) {
        // 9 coalesced LDG.32 (3 planes x 3 chunks)
        const float* P0 = &g_xT[(size_t)(t * 3 + 0) * B_TOTAL];
        const float* P1 = &g_xT[(size_t)(t * 3 + 1) * B_TOTAL];
        const float* P2 = &g_xT[(size_t)(t * 3 + 2) * B_TOTAL];
        const float x0a = P0[ea], x0b = P0[eb], x0c = P0[ec];
        const float x1a = P1[ea], x1b = P1[eb], x1c = P1[ec];
        const float x2a = P2[ea], x2b = P2[eb], x2c = P2[ec];

        float hna[11], hnb[11], hnc[11];
        const float* wd = ws + 528 + t * 88;

        #pragma unroll
        for (int j = 0; j < 11; j++) {
            const float* W = ws + j * 48;
            float w;
            w = W[0]; float aza = w, azb = w, azc = w;
            w = W[1]; float ara = w, arb = w, arc = w;
            w = W[2]; float aha = w, ahb = w, ahc = w;
            w = W[3]; float bha = w, bhb = w, bhc = w;
            w = W[4];  aza = fmaf(x0a, w, aza); azb = fmaf(x0b, w, azb); azc = fmaf(x0c, w, azc);
            w = W[5];  aza = fmaf(x1a, w, aza); azb = fmaf(x1b, w, azb); azc = fmaf(x1c, w, azc);
            w = W[6];  aza = fmaf(x2a, w, aza); azb = fmaf(x2b, w, azb); azc = fmaf(x2c, w, azc);
            w = W[7];  ara = fmaf(x0a, w, ara); arb = fmaf(x0b, w, arb); arc = fmaf(x0c, w, arc);
            w = W[8];  ara = fmaf(x1a, w, ara); arb = fmaf(x1b, w, arb); arc = fmaf(x1c, w, arc);
            w = W[9];  ara = fmaf(x2a, w, ara); arb = fmaf(x2b, w, arb); arc = fmaf(x2c, w, arc);
            w = W[10]; aha = fmaf(x0a, w, aha); ahb = fmaf(x0b, w, ahb); ahc = fmaf(x0c, w, ahc);
            w = W[11]; aha = fmaf(x1a, w, aha); ahb = fmaf(x1b, w, ahb); ahc = fmaf(x1c, w, ahc);
            w = W[12]; aha = fmaf(x2a, w, aha); ahb = fmaf(x2b, w, ahb); ahc = fmaf(x2c, w, ahc);
            #pragma unroll
            for (int i = 0; i < 11; i++) {
                w = W[14 + i];
                aza = fmaf(ha[i], w, aza); azb = fmaf(hb[i], w, azb); azc = fmaf(hc[i], w, azc);
                w = W[25 + i];
                ara = fmaf(ha[i], w, ara); arb = fmaf(hb[i], w, arb); arc = fmaf(hc[i], w, arc);
                w = W[36 + i];
                bha = fmaf(ha[i], w, bha); bhb = fmaf(hb[i], w, bhb); bhc = fmaf(hc[i], w, bhc);
            }
            float za = sig1(aza), zb = sig1(azb), zc = sig1(azc);
            float ra = sig1(ara), rb = sig1(arb), rc = sig1(arc);
            float hha = tnh1(fmaf(ra, bha, aha));
            float hhb = tnh1(fmaf(rb, bhb, ahb));
            float hhc = tnh1(fmaf(rc, bhc, ahc));
            float nha = fmaf(za, ha[j] - hha, hha);
            float nhb = fmaf(zb, hb[j] - hhb, hhb);
            float nhc = fmaf(zc, hc[j] - hhc, hhc);
            hna[j] = nha; hnb[j] = nhb; hnc[j] = nhc;

            const float* wj = wd + j * 8;
            #pragma unroll
            for (int c = 0; c < 7; c++) {
                w = wj[c];
                aca[c]  = fmaf(nha, w, aca[c]);
                acb[c]  = fmaf(nhb, w, acb[c]);
                acc_[c] = fmaf(nhc, w, acc_[c]);
            }
        }
        #pragma unroll
        for (int i = 0; i < 11; i++) {
            ha[i] = hna[i]; hb[i] = hnb[i]; hc[i] = hnc[i];
        }
    }

    // softmax per element + coalesced-ish scalar stores
    {
        float m = aca[0];
        #pragma unroll
        for (int c = 1; c < 7; c++) m = fmaxf(m, aca[c]);
        float ex[7], s = 0.0f;
        #pragma unroll
        for (int c = 0; c < 7; c++) { ex[c] = fex2((aca[c] - m) * LOG2E); s += ex[c]; }
        float inv = frcp(s);
        float* o = out + (size_t)ea * 7;
        #pragma unroll
        for (int c = 0; c < 7; c++) o[c] = ex[c] * inv;
    }
    {
        float m = acb[0];
        #pragma unroll
        for (int c = 1; c < 7; c++) m = fmaxf(m, acb[c]);
        float ex[7], s = 0.0f;
        #pragma unroll
        for (int c = 0; c < 7; c++) { ex[c] = fex2((acb[c] - m) * LOG2E); s += ex[c]; }
        float inv = frcp(s);
        float* o = out + (size_t)eb * 7;
        #pragma unroll
        for (int c = 0; c < 7; c++) o[c] = ex[c] * inv;
    }
    if (cok) {
        float m = acc_[0];
        #pragma unroll
        for (int c = 1; c < 7; c++) m = fmaxf(m, acc_[c]);
        float ex[7], s = 0.0f;
        #pragma unroll
        for (int c = 0; c < 7; c++) { ex[c] = fex2((acc_[c] - m) * LOG2E); s += ex[c]; }
        float inv = frcp(s);
        float* o = out + (size_t)ecv * 7;
        #pragma unroll
        for (int c = 0; c < 7; c++) o[c] = ex[c] * inv;
    }
}

// ---------------- launch ----------------
extern "C" void kernel_launch(void* const* d_in, const int* in_sizes, int n_in,
                              void* d_out, int out_size) {
    const float* x    = (const float*)d_in[0];   // [B, 11, 3]
    const float* K    = (const float*)d_in[1];   // [3, 33]
    const float* R    = (const float*)d_in[2];   // [11, 33]
    const float* bias = (const float*)d_in[3];   // [2, 33]
    const float* Wd   = (const float*)d_in[4];   // [121, 7]
    const float* db   = (const float*)d_in[5];   // [7]
    float* out = (float*)d_out;                  // [B, 7]

    xpose_kernel<<<B_TOTAL / TP_ELEMS, 256>>>(x, K, R, bias, Wd, db);
    const int nblk = (NTHREADS_TOTAL + NTHREADS - 1) / NTHREADS;
    gru_main<<<nblk, NTHREADS>>>(out);
}

// round 15
// speedup vs baseline: 6.3085x; 6.3085x over previous
#include <cuda_runtime.h>

// ============================================================================
// RNN_29463475650831: GRU(T=11,F=3,H=11, reset_after) + Dense(121->7) + softmax
// B = 1,048,576. fp32. R14: R9 structure (scalar 4 elems/thread, 255-reg,
// 2 blk/SM, MUFU.TANH) with weights in __constant__ memory instead of smem.
// Warp-uniform constant loads -> LDCU/uniform-register path: frees regular
// registers (kills residual spills) and removes LDS port contention.
// ============================================================================

#define NTHREADS 128
#define B_TOTAL 1048576
#define LOG2E 1.4426950408889634f

// Scalar weight image layout (floats):
// region A: 48/j (11 j): 0:bz 1:br 2:bh_in 3:bh_rec 4-6:Kz 7-9:Kr 10-12:Kh
//                        13:pad 14-24:Rz 25-35:Rr 36-46:Rh 47:pad
// region D (528+): 8/(t,j): Wd[0..6],pad ; region Db (1496+): dense bias
#define WTOTF 1504
__device__   __align__(16) float g_wimg[WTOTF];   // staging (built on device)
__constant__ __align__(16) float c_wimg[WTOTF];   // consumed by gru_main

// Transposed input: plane layout [t*3+f][elem]  (33 planes of B floats)
__device__ __align__(16) float g_xT[33u * B_TOTAL];   // 138 MB static scratch

// ---------------- scalar math helpers ----------------
static __device__ __forceinline__ float fex2(float x) {
    float y; asm("ex2.approx.f32 %0, %1;" : "=f"(y) : "f"(x)); return y;
}
static __device__ __forceinline__ float frcp(float x) {
    float y; asm("rcp.approx.f32 %0, %1;" : "=f"(y) : "f"(x)); return y;
}
static __device__ __forceinline__ float tnh1(float x) {       // MUFU.TANH
    float y; asm("tanh.approx.f32 %0, %1;" : "=f"(y) : "f"(x)); return y;
}
static __device__ __forceinline__ float sig1(float a) {       // 0.5+0.5*tanh(a/2)
    return fmaf(0.5f, tnh1(0.5f * a), 0.5f);
}

// ---------------- weight image builder ----------------
static __device__ __forceinline__ float wval(int i,
                                             const float* K, const float* R,
                                             const float* bias, const float* Wd,
                                             const float* db) {
    float v = 0.0f;
    if (i < 528) {
        int j = i / 48, k = i % 48;
        if      (k == 0)  v = bias[j]      + bias[33 + j];
        else if (k == 1)  v = bias[11 + j] + bias[44 + j];
        else if (k == 2)  v = bias[22 + j];
        else if (k == 3)  v = bias[55 + j];
        else if (k < 7)   v = K[(k - 4)  * 33 + j];
        else if (k < 10)  v = K[(k - 7)  * 33 + 11 + j];
        else if (k < 13)  v = K[(k - 10) * 33 + 22 + j];
        else if (k == 13) v = 0.0f;
        else if (k < 25)  v = R[(k - 14) * 33 + j];
        else if (k < 36)  v = R[(k - 25) * 33 + 11 + j];
        else if (k < 47)  v = R[(k - 36) * 33 + 22 + j];
    } else if (i < 1496) {
        int d = i - 528, c = d & 7;
        if (c < 7) v = Wd[(d >> 3) * 7 + c];
    } else {
        int c = i - 1496;
        if (c < 7) v = db[c];
    }
    return v;
}

// ---------------- kernel 1: transpose x + (block 0) build weight image ------
#define TP_ELEMS 256
__global__ __launch_bounds__(256)
void xpose_kernel(const float* __restrict__ x,
                  const float* __restrict__ K, const float* __restrict__ R,
                  const float* __restrict__ bias, const float* __restrict__ Wd,
                  const float* __restrict__ db) {
    __shared__ float tile[TP_ELEMS * 33];
    const unsigned base = blockIdx.x * (TP_ELEMS * 33u);
    #pragma unroll
    for (int k = 0; k < 33; k++) {
        int i = k * 256 + threadIdx.x;
        tile[i] = x[base + i];
    }
    if (blockIdx.x == 0) {
        for (int i = threadIdx.x; i < WTOTF; i += 256) {
            g_wimg[i] = wval(i, K, R, bias, Wd, db);
        }
    }
    __syncthreads();
    const unsigned ebase = blockIdx.x * TP_ELEMS;
    #pragma unroll 4
    for (int idx = threadIdx.x; idx < 33 * TP_ELEMS; idx += 256) {
        int plane = idx / TP_ELEMS;          // 0..32
        int el    = idx % TP_ELEMS;          // 0..255 -> coalesced write
        g_xT[(size_t)plane * B_TOTAL + ebase + el] = tile[el * 33 + plane];
    }
}

// ---------------- kernel 2: main GRU (scalar 4 elems, constant weights) -----
__global__ __launch_bounds__(NTHREADS, 2)   // 255-reg budget
void gru_main(float* __restrict__ out) {
    const unsigned q = blockIdx.x * NTHREADS + threadIdx.x;   // quad index
    const unsigned e0 = 4u * q;                               // elements e0..e0+3

    float ha[11], hb[11], hc[11], hd[11];
    #pragma unroll
    for (int i = 0; i < 11; i++) { ha[i] = hb[i] = hc[i] = hd[i] = 0.0f; }

    float aca[7], acb[7], acc_[7], acd[7];
    #pragma unroll
    for (int c = 0; c < 7; c++) {
        float b = c_wimg[1496 + c];
        aca[c] = b; acb[c] = b; acc_[c] = b; acd[c] = b;
    }

    #pragma unroll 1
    for (int t = 0; t < 11; t++) {
        // coalesced LDG.128: 4 adjacent elements within each plane
        const float4 X0 = *reinterpret_cast<const float4*>(&g_xT[(size_t)(t * 3 + 0) * B_TOTAL + e0]);
        const float4 X1 = *reinterpret_cast<const float4*>(&g_xT[(size_t)(t * 3 + 1) * B_TOTAL + e0]);
        const float4 X2 = *reinterpret_cast<const float4*>(&g_xT[(size_t)(t * 3 + 2) * B_TOTAL + e0]);

        float hna[11], hnb[11], hnc[11], hnd[11];
        const float* wd = c_wimg + 528 + t * 88;

        #pragma unroll
        for (int j = 0; j < 11; j++) {
            const float* W = c_wimg + j * 48;
            float w;
            w = W[0]; float aza = w, azb = w, azc = w, azd = w;
            w = W[1]; float ara = w, arb = w, arc = w, ard = w;
            w = W[2]; float aha = w, ahb = w, ahc = w, ahd = w;
            w = W[3]; float bha = w, bhb = w, bhc = w, bhd = w;
            w = W[4];  aza = fmaf(X0.x, w, aza); azb = fmaf(X0.y, w, azb);
                       azc = fmaf(X0.z, w, azc); azd = fmaf(X0.w, w, azd);
            w = W[5];  aza = fmaf(X1.x, w, aza); azb = fmaf(X1.y, w, azb);
                       azc = fmaf(X1.z, w, azc); azd = fmaf(X1.w, w, azd);
            w = W[6];  aza = fmaf(X2.x, w, aza); azb = fmaf(X2.y, w, azb);
                       azc = fmaf(X2.z, w, azc); azd = fmaf(X2.w, w, azd);
            w = W[7];  ara = fmaf(X0.x, w, ara); arb = fmaf(X0.y, w, arb);
                       arc = fmaf(X0.z, w, arc); ard = fmaf(X0.w, w, ard);
            w = W[8];  ara = fmaf(X1.x, w, ara); arb = fmaf(X1.y, w, arb);
                       arc = fmaf(X1.z, w, arc); ard = fmaf(X1.w, w, ard);
            w = W[9];  ara = fmaf(X2.x, w, ara); arb = fmaf(X2.y, w, arb);
                       arc = fmaf(X2.z, w, arc); ard = fmaf(X2.w, w, ard);
            w = W[10]; aha = fmaf(X0.x, w, aha); ahb = fmaf(X0.y, w, ahb);
                       ahc = fmaf(X0.z, w, ahc); ahd = fmaf(X0.w, w, ahd);
            w = W[11]; aha = fmaf(X1.x, w, aha); ahb = fmaf(X1.y, w, ahb);
                       ahc = fmaf(X1.z, w, ahc); ahd = fmaf(X1.w, w, ahd);
            w = W[12]; aha = fmaf(X2.x, w, aha); ahb = fmaf(X2.y, w, ahb);
                       ahc = fmaf(X2.z, w, ahc); ahd = fmaf(X2.w, w, ahd);
            #pragma unroll
            for (int i = 0; i < 11; i++) {
                w = W[14 + i];
                aza = fmaf(ha[i], w, aza); azb = fmaf(hb[i], w, azb);
                azc = fmaf(hc[i], w, azc); azd = fmaf(hd[i], w, azd);
                w = W[25 + i];
                ara = fmaf(ha[i], w, ara); arb = fmaf(hb[i], w, arb);
                arc = fmaf(hc[i], w, arc); ard = fmaf(hd[i], w, ard);
                w = W[36 + i];
                bha = fmaf(ha[i], w, bha); bhb = fmaf(hb[i], w, bhb);
                bhc = fmaf(hc[i], w, bhc); bhd = fmaf(hd[i], w, bhd);
            }
            float za = sig1(aza), zb = sig1(azb), zc = sig1(azc), zd = sig1(azd);
            float ra = sig1(ara), rb = sig1(arb), rc = sig1(arc), rd = sig1(ard);
            float hha = tnh1(fmaf(ra, bha, aha));
            float hhb = tnh1(fmaf(rb, bhb, ahb));
            float hhc = tnh1(fmaf(rc, bhc, ahc));
            float hhd = tnh1(fmaf(rd, bhd, ahd));
            float nha = fmaf(za, ha[j] - hha, hha);
            float nhb = fmaf(zb, hb[j] - hhb, hhb);
            float nhc = fmaf(zc, hc[j] - hhc, hhc);
            float nhd = fmaf(zd, hd[j] - hhd, hhd);
            hna[j] = nha; hnb[j] = nhb; hnc[j] = nhc; hnd[j] = nhd;

            const float* wj = wd + j * 8;
            #pragma unroll
            for (int c = 0; c < 7; c++) {
                w = wj[c];
                aca[c]  = fmaf(nha, w, aca[c]);
                acb[c]  = fmaf(nhb, w, acb[c]);
                acc_[c] = fmaf(nhc, w, acc_[c]);
                acd[c]  = fmaf(nhd, w, acd[c]);
            }
        }
        #pragma unroll
        for (int i = 0; i < 11; i++) {
            ha[i] = hna[i]; hb[i] = hnb[i]; hc[i] = hnc[i]; hd[i] = hnd[i];
        }
    }

    // softmax per element; 28 contiguous floats -> 7 aligned STG.128
    float r28[28];
    {
        const float* A[4] = { aca, acb, acc_, acd };
        #pragma unroll
        for (int v = 0; v < 4; v++) {
            const float* a = A[v];
            float m = a[0];
            #pragma unroll
            for (int c = 1; c < 7; c++) m = fmaxf(m, a[c]);
            float ex[7], s = 0.0f;
            #pragma unroll
            for (int c = 0; c < 7; c++) { ex[c] = fex2((a[c] - m) * LOG2E); s += ex[c]; }
            float inv = frcp(s);
            #pragma unroll
            for (int c = 0; c < 7; c++) r28[v * 7 + c] = ex[c] * inv;
        }
    }
    float4* o4 = reinterpret_cast<float4*>(out + (size_t)e0 * 7);   // 112B, 16B-aligned
    #pragma unroll
    for (int k = 0; k < 7; k++)
        o4[k] = make_float4(r28[4 * k], r28[4 * k + 1], r28[4 * k + 2], r28[4 * k + 3]);
}

// ---------------- launch ----------------
extern "C" void kernel_launch(void* const* d_in, const int* in_sizes, int n_in,
                              void* d_out, int out_size) {
    const float* x    = (const float*)d_in[0];   // [B, 11, 3]
    const float* K    = (const float*)d_in[1];   // [3, 33]
    const float* R    = (const float*)d_in[2];   // [11, 33]
    const float* bias = (const float*)d_in[3];   // [2, 33]
    const float* Wd   = (const float*)d_in[4];   // [121, 7]
    const float* db   = (const float*)d_in[5];   // [7]
    float* out = (float*)d_out;                  // [B, 7]

    // 1) build weight image (device) + transpose x
    xpose_kernel<<<B_TOTAL / TP_ELEMS, 256>>>(x, K, R, bias, Wd, db);

    // 2) install weight image into __constant__ (graph-capturable D2D memcpy)
    void* wsrc = nullptr;
    cudaGetSymbolAddress(&wsrc, g_wimg);
    cudaMemcpyToSymbolAsync(c_wimg, wsrc, WTOTF * sizeof(float), 0,
                            cudaMemcpyDeviceToDevice);

    // 3) main kernel
    gru_main<<<(B_TOTAL / 4) / NTHREADS, NTHREADS>>>(out);
}

// round 17
// speedup vs baseline: 7.5867x; 1.2026x over previous
#include <cuda_runtime.h>

// ============================================================================
// RNN_29463475650831: GRU(T=11,F=3,H=11, reset_after) + Dense(121->7) + softmax
// B = 1,048,576. fp32. R16: constant-memory weights (R14 win) + 3 elems/thread
// @ 168-reg budget -> 12 warps/SM (LDCU temps live in UR file, so 3-elem now
// fits where R13-smem spilled). Sigmoid 0.5-prescale folded into z/r weights.
// ============================================================================

#define NTHREADS 128
#define B_TOTAL 1048576
#define CHUNK 349526                       // ceil(B/3)
#define NTHREADS_TOTAL CHUNK
#define LOG2E 1.4426950408889634f

// Scalar weight image layout (floats):
// region A: 48/j (11 j): 0:bz*.5 1:br*.5 2:bh_in 3:bh_rec 4-6:Kz*.5 7-9:Kr*.5
//                        10-12:Kh 13:pad 14-24:Rz*.5 25-35:Rr*.5 36-46:Rh 47:pad
// region D (528+): 8/(t,j): Wd[0..6],pad ; region Db (1496+): dense bias
#define WTOTF 1504
__device__   __align__(16) float g_wimg[WTOTF];   // staging (built on device)
__constant__ __align__(16) float c_wimg[WTOTF];   // consumed by gru_main

// Transposed input: plane layout [t*3+f][elem]  (33 planes of B floats)
__device__ __align__(16) float g_xT[33u * B_TOTAL];   // 138 MB static scratch

// ---------------- scalar math helpers ----------------
static __device__ __forceinline__ float fex2(float x) {
    float y; asm("ex2.approx.f32 %0, %1;" : "=f"(y) : "f"(x)); return y;
}
static __device__ __forceinline__ float frcp(float x) {
    float y; asm("rcp.approx.f32 %0, %1;" : "=f"(y) : "f"(x)); return y;
}
static __device__ __forceinline__ float tnh1(float x) {       // MUFU.TANH
    float y; asm("tanh.approx.f32 %0, %1;" : "=f"(y) : "f"(x)); return y;
}
// sigmoid with the 0.5 input prescale already folded into the weights:
// az was accumulated as 0.5*(Wx+Rh+b)  ->  sigmoid = 0.5*tanh(az) + 0.5
static __device__ __forceinline__ float sigp(float a_half) {
    return fmaf(0.5f, tnh1(a_half), 0.5f);
}

// ---------------- weight image builder (z/r entries pre-scaled by 0.5) ------
static __device__ __forceinline__ float wval(int i,
                                             const float* K, const float* R,
                                             const float* bias, const float* Wd,
                                             const float* db) {
    float v = 0.0f;
    if (i < 528) {
        int j = i / 48, k = i % 48;
        if      (k == 0)  v = 0.5f * (bias[j]      + bias[33 + j]);   // bz
        else if (k == 1)  v = 0.5f * (bias[11 + j] + bias[44 + j]);   // br
        else if (k == 2)  v = bias[22 + j];
        else if (k == 3)  v = bias[55 + j];
        else if (k < 7)   v = 0.5f * K[(k - 4)  * 33 + j];            // Kz
        else if (k < 10)  v = 0.5f * K[(k - 7)  * 33 + 11 + j];       // Kr
        else if (k < 13)  v = K[(k - 10) * 33 + 22 + j];              // Kh
        else if (k == 13) v = 0.0f;
        else if (k < 25)  v = 0.5f * R[(k - 14) * 33 + j];            // Rz
        else if (k < 36)  v = 0.5f * R[(k - 25) * 33 + 11 + j];       // Rr
        else if (k < 47)  v = R[(k - 36) * 33 + 22 + j];              // Rh
    } else if (i < 1496) {
        int d = i - 528, c = d & 7;
        if (c < 7) v = Wd[(d >> 3) * 7 + c];
    } else {
        int c = i - 1496;
        if (c < 7) v = db[c];
    }
    return v;
}

// ---------------- kernel 1: transpose x + (block 0) build weight image ------
#define TP_ELEMS 256
__global__ __launch_bounds__(256)
void xpose_kernel(const float* __restrict__ x,
                  const float* __restrict__ K, const float* __restrict__ R,
                  const float* __restrict__ bias, const float* __restrict__ Wd,
                  const float* __restrict__ db) {
    __shared__ float tile[TP_ELEMS * 33];
    const unsigned base = blockIdx.x * (TP_ELEMS * 33u);
    #pragma unroll
    for (int k = 0; k < 33; k++) {
        int i = k * 256 + threadIdx.x;
        tile[i] = x[base + i];
    }
    if (blockIdx.x == 0) {
        for (int i = threadIdx.x; i < WTOTF; i += 256) {
            g_wimg[i] = wval(i, K, R, bias, Wd, db);
        }
    }
    __syncthreads();
    const unsigned ebase = blockIdx.x * TP_ELEMS;
    #pragma unroll 4
    for (int idx = threadIdx.x; idx < 33 * TP_ELEMS; idx += 256) {
        int plane = idx / TP_ELEMS;
        int el    = idx % TP_ELEMS;
        g_xT[(size_t)plane * B_TOTAL + ebase + el] = tile[el * 33 + plane];
    }
}

// ---------------- kernel 2: main GRU (scalar 3 elems, constant weights) -----
__global__ __launch_bounds__(NTHREADS, 3)   // 168-reg budget, 12 warps/SM
void gru_main(float* __restrict__ out) {
    const unsigned q = blockIdx.x * NTHREADS + threadIdx.x;
    if (q >= NTHREADS_TOTAL) return;
    const unsigned ea = q;                        // chunk 0
    const unsigned eb = q + CHUNK;                // chunk 1
    const unsigned ecv = q + 2u * CHUNK;          // chunk 2 (may overflow by <=2)
    const bool cok = (ecv < B_TOTAL);
    const unsigned ec = cok ? ecv : (B_TOTAL - 1u);

    float ha[11], hb[11], hc[11];
    #pragma unroll
    for (int i = 0; i < 11; i++) { ha[i] = hb[i] = hc[i] = 0.0f; }

    float aca[7], acb[7], acc_[7];
    #pragma unroll
    for (int c = 0; c < 7; c++) {
        float b = c_wimg[1496 + c];
        aca[c] = b; acb[c] = b; acc_[c] = b;
    }

    #pragma unroll 1
    for (int t = 0; t < 11; t++) {
        const float* P0 = &g_xT[(size_t)(t * 3 + 0) * B_TOTAL];
        const float* P1 = &g_xT[(size_t)(t * 3 + 1) * B_TOTAL];
        const float* P2 = &g_xT[(size_t)(t * 3 + 2) * B_TOTAL];
        const float x0a = P0[ea], x0b = P0[eb], x0c = P0[ec];
        const float x1a = P1[ea], x1b = P1[eb], x1c = P1[ec];
        const float x2a = P2[ea], x2b = P2[eb], x2c = P2[ec];

        float hna[11], hnb[11], hnc[11];
        const float* wd = c_wimg + 528 + t * 88;

        #pragma unroll
        for (int j = 0; j < 11; j++) {
            const float* W = c_wimg + j * 48;
            float w;
            w = W[0]; float aza = w, azb = w, azc = w;   // pre-scaled by 0.5
            w = W[1]; float ara = w, arb = w, arc = w;   // pre-scaled by 0.5
            w = W[2]; float aha = w, ahb = w, ahc = w;
            w = W[3]; float bha = w, bhb = w, bhc = w;
            w = W[4];  aza = fmaf(x0a, w, aza); azb = fmaf(x0b, w, azb); azc = fmaf(x0c, w, azc);
            w = W[5];  aza = fmaf(x1a, w, aza); azb = fmaf(x1b, w, azb); azc = fmaf(x1c, w, azc);
            w = W[6];  aza = fmaf(x2a, w, aza); azb = fmaf(x2b, w, azb); azc = fmaf(x2c, w, azc);
            w = W[7];  ara = fmaf(x0a, w, ara); arb = fmaf(x0b, w, arb); arc = fmaf(x0c, w, arc);
            w = W[8];  ara = fmaf(x1a, w, ara); arb = fmaf(x1b, w, arb); arc = fmaf(x1c, w, arc);
            w = W[9];  ara = fmaf(x2a, w, ara); arb = fmaf(x2b, w, arb); arc = fmaf(x2c, w, arc);
            w = W[10]; aha = fmaf(x0a, w, aha); ahb = fmaf(x0b, w, ahb); ahc = fmaf(x0c, w, ahc);
            w = W[11]; aha = fmaf(x1a, w, aha); ahb = fmaf(x1b, w, ahb); ahc = fmaf(x1c, w, ahc);
            w = W[12]; aha = fmaf(x2a, w, aha); ahb = fmaf(x2b, w, ahb); ahc = fmaf(x2c, w, ahc);
            #pragma unroll
            for (int i = 0; i < 11; i++) {
                w = W[14 + i];
                aza = fmaf(ha[i], w, aza); azb = fmaf(hb[i], w, azb); azc = fmaf(hc[i], w, azc);
                w = W[25 + i];
                ara = fmaf(ha[i], w, ara); arb = fmaf(hb[i], w, arb); arc = fmaf(hc[i], w, arc);
                w = W[36 + i];
                bha = fmaf(ha[i], w, bha); bhb = fmaf(hb[i], w, bhb); bhc = fmaf(hc[i], w, bhc);
            }
            float za = sigp(aza), zb = sigp(azb), zc = sigp(azc);
            float ra = sigp(ara), rb = sigp(arb), rc = sigp(arc);
            float hha = tnh1(fmaf(ra, bha, aha));
            float hhb = tnh1(fmaf(rb, bhb, ahb));
            float hhc = tnh1(fmaf(rc, bhc, ahc));
            float nha = fmaf(za, ha[j] - hha, hha);
            float nhb = fmaf(zb, hb[j] - hhb, hhb);
            float nhc = fmaf(zc, hc[j] - hhc, hhc);
            hna[j] = nha; hnb[j] = nhb; hnc[j] = nhc;

            const float* wj = wd + j * 8;
            #pragma unroll
            for (int c = 0; c < 7; c++) {
                w = wj[c];
                aca[c]  = fmaf(nha, w, aca[c]);
                acb[c]  = fmaf(nhb, w, acb[c]);
                acc_[c] = fmaf(nhc, w, acc_[c]);
            }
        }
        #pragma unroll
        for (int i = 0; i < 11; i++) {
            ha[i] = hna[i]; hb[i] = hnb[i]; hc[i] = hnc[i];
        }
    }

    // softmax per element + stores (coalesced within each chunk)
    {
        float m = aca[0];
        #pragma unroll
        for (int c = 1; c < 7; c++) m = fmaxf(m, aca[c]);
        float ex[7], s = 0.0f;
        #pragma unroll
        for (int c = 0; c < 7; c++) { ex[c] = fex2((aca[c] - m) * LOG2E); s += ex[c]; }
        float inv = frcp(s);
        float* o = out + (size_t)ea * 7;
        #pragma unroll
        for (int c = 0; c < 7; c++) o[c] = ex[c] * inv;
    }
    {
        float m = acb[0];
        #pragma unroll
        for (int c = 1; c < 7; c++) m = fmaxf(m, acb[c]);
        float ex[7], s = 0.0f;
        #pragma unroll
        for (int c = 0; c < 7; c++) { ex[c] = fex2((acb[c] - m) * LOG2E); s += ex[c]; }
        float inv = frcp(s);
        float* o = out + (size_t)eb * 7;
        #pragma unroll
        for (int c = 0; c < 7; c++) o[c] = ex[c] * inv;
    }
    if (cok) {
        float m = acc_[0];
        #pragma unroll
        for (int c = 1; c < 7; c++) m = fmaxf(m, acc_[c]);
        float ex[7], s = 0.0f;
        #pragma unroll
        for (int c = 0; c < 7; c++) { ex[c] = fex2((acc_[c] - m) * LOG2E); s += ex[c]; }
        float inv = frcp(s);
        float* o = out + (size_t)ecv * 7;
        #pragma unroll
        for (int c = 0; c < 7; c++) o[c] = ex[c] * inv;
    }
}

// ---------------- launch ----------------
extern "C" void kernel_launch(void* const* d_in, const int* in_sizes, int n_in,
                              void* d_out, int out_size) {
    const float* x    = (const float*)d_in[0];   // [B, 11, 3]
    const float* K    = (const float*)d_in[1];   // [3, 33]
    const float* R    = (const float*)d_in[2];   // [11, 33]
    const float* bias = (const float*)d_in[3];   // [2, 33]
    const float* Wd   = (const float*)d_in[4];   // [121, 7]
    const float* db   = (const float*)d_in[5];   // [7]
    float* out = (float*)d_out;                  // [B, 7]

    // 1) build weight image (device) + transpose x
    xpose_kernel<<<B_TOTAL / TP_ELEMS, 256>>>(x, K, R, bias, Wd, db);

    // 2) install weight image into __constant__ (graph-capturable D2D memcpy)
    void* wsrc = nullptr;
    cudaGetSymbolAddress(&wsrc, g_wimg);
    cudaMemcpyToSymbolAsync(c_wimg, wsrc, WTOTF * sizeof(float), 0,
                            cudaMemcpyDeviceToDevice);

    // 3) main kernel
    const int nblk = (NTHREADS_TOTAL + NTHREADS - 1) / NTHREADS;
    gru_main<<<nblk, NTHREADS>>>(out);
}